// round 5
// baseline (speedup 1.0000x reference)
#include <cuda_runtime.h>

#define Hh 126
#define Ww 126
#define WP 128
#define NPIX (Hh*Ww)        // 15876
#define PLANE (Hh*WP)       // 16128
#define NLAYER 6

// ping-pong activation buffers + involution weight buffer
__device__ float g_x[64*PLANE];     // ~4.1 MB
__device__ float g_y[64*PLANE];     // ~4.1 MB
__device__ float g_w[196*PLANE];    // ~12.6 MB

// ---------------------------------------------------------------------------
// conv_in: (1,3,128,128) -> (1,64,126,126), 3x3 valid conv
// ---------------------------------------------------------------------------
__global__ __launch_bounds__(256) void k_conv_in(const float* __restrict__ in,
                                                 const float* __restrict__ wt,
                                                 const float* __restrict__ bias,
                                                 float* __restrict__ out)
{
    int t = blockIdx.x * 256 + threadIdx.x;      // over 126*128 padded plane
    int c = blockIdx.y;
    int y = t >> 7, x = t & 127;
    if (y >= Hh || x >= Ww) return;
    float acc = bias[c];
    const float* wc = wt + c * 27;
    #pragma unroll
    for (int i = 0; i < 3; i++)
        #pragma unroll
        for (int r = 0; r < 3; r++)
            #pragma unroll
            for (int s = 0; s < 3; s++)
                acc += wc[(i*3+r)*3+s] * in[(i*128 + (y+r))*128 + (x+s)];
    out[c*PLANE + y*WP + x] = acc;
}

// ---------------------------------------------------------------------------
// kgen v4: 256 threads / 16 pixels, 16 threads per pixel.
// ---------------------------------------------------------------------------
__global__ __launch_bounds__(256) void k_kgen(const float* __restrict__ src,
    const float* __restrict__ wr, const float* __restrict__ br,
    const float* __restrict__ gmm, const float* __restrict__ bet,
    const float* __restrict__ mu, const float* __restrict__ var,
    const float* __restrict__ ws, const float* __restrict__ bs)
{
    __shared__ alignas(16) float xs2[16*68];     // [p][ic] pad 68
    __shared__ alignas(16) float wrs2[16*68];    // [c][ic] pad 68
    __shared__ alignas(16) float wsj[196*16];    // [j][c] native layout
    __shared__ alignas(16) float bss[196];
    __shared__ alignas(16) float ts[16*20];      // [p][c] pad 20
    __shared__ float scs[16], shs[16];

    int tid = threadIdx.x;
    int pix0 = blockIdx.x * 16;
    int p = tid & 15;
    int c = tid >> 4;

    for (int i = tid; i < 1024; i += 256) wrs2[(i >> 6)*68 + (i & 63)] = wr[i];
    for (int i = tid; i < 3136; i += 256) wsj[i] = ws[i];
    if (tid < 196) bss[tid] = bs[tid];
    if (tid < 16) {
        float s = gmm[tid] * rsqrtf(var[tid] + 1e-5f);
        scs[tid] = s;
        shs[tid] = (br[tid] - mu[tid]) * s + bet[tid];
    }
    for (int i = tid; i < 1024; i += 256) {
        int ic = i >> 4, pp = i & 15;
        int px2 = pix0 + pp;
        float v = 0.f;
        if (px2 < NPIX) {
            int y2 = px2 / 126;
            v = src[ic*PLANE + y2*WP + (px2 - y2*126)];
        }
        xs2[pp*68 + ic] = v;
    }
    __syncthreads();

    // Phase A
    {
        float a = 0.f;
        #pragma unroll
        for (int i4 = 0; i4 < 16; i4++) {
            float4 xv = *(const float4*)&xs2[p*68 + i4*4];
            float4 wv = *(const float4*)&wrs2[c*68 + i4*4];
            a += xv.x*wv.x + xv.y*wv.y + xv.z*wv.z + xv.w*wv.w;
        }
        ts[p*20 + c] = fmaxf(a * scs[c] + shs[c], 0.f);
    }
    __syncthreads();

    // Phase B
    float t[16];
    #pragma unroll
    for (int k = 0; k < 4; k++) {
        float4 v = *(const float4*)&ts[p*20 + k*4];
        t[k*4] = v.x; t[k*4+1] = v.y; t[k*4+2] = v.z; t[k*4+3] = v.w;
    }
    int pix = pix0 + p;
    bool valid = pix < NPIX;
    int addr = 0;
    if (valid) { int yy = pix / 126; addr = yy*WP + (pix - yy*126); }

    #pragma unroll 1
    for (int j = c; j < 196; j += 16) {
        const float4* wv = (const float4*)&wsj[j*16];
        float4 w0 = wv[0], w1 = wv[1], w2 = wv[2], w3 = wv[3];
        float acc = bss[j];
        acc += w0.x*t[0]  + w0.y*t[1]  + w0.z*t[2]  + w0.w*t[3];
        acc += w1.x*t[4]  + w1.y*t[5]  + w1.z*t[6]  + w1.w*t[7];
        acc += w2.x*t[8]  + w2.y*t[9]  + w2.z*t[10] + w2.w*t[11];
        acc += w3.x*t[12] + w3.y*t[13] + w3.z*t[14] + w3.w*t[15];
        if (valid) g_w[j*PLANE + addr] = acc;
    }
}

// ---------------------------------------------------------------------------
// agg v4: 32x8 tile, 8 ch/block, 1 px x 8 ch per thread, 256 threads.
// Warp maps to one smem row -> linear addressing, no swizzle needed.
// grid (4, 16, 8).
// ---------------------------------------------------------------------------
#define AGG_PCH 40            // chunks (=4ch groups) per row, 38 used

__global__ __launch_bounds__(256) void k_agg(const float* __restrict__ src,
                                             float* __restrict__ dst)
{
    __shared__ alignas(16) float xs[14*2*AGG_PCH*4];   // [row][c4][chunk][4]

    int g    = blockIdx.z >> 1;
    int half = blockIdx.z & 1;
    int x0 = blockIdx.x * 32, y0 = blockIdx.y * 8;
    int tid = threadIdx.x;

    // loader: 8 ch x 14 rows x 38 cols
    for (int i = tid; i < 8*14*38; i += 256) {
        int c = i / 532; int rem = i - c*532;
        int r = rem / 38; int pp = rem - r*38;
        int gy = y0 + r - 3, gx = x0 + pp - 3;
        float v = 0.f;
        if ((unsigned)gy < 126u && (unsigned)gx < 126u)
            v = src[(g*16 + half*8 + c)*PLANE + gy*WP + gx];
        xs[((r*2 + (c >> 2))*AGG_PCH + pp)*4 + (c & 3)] = v;
    }
    __syncthreads();

    int ty = tid >> 5;            // 0..7  (warp-uniform)
    int xp = tid & 31;            // 0..31
    int gy = y0 + ty;
    if (gy >= 126) return;
    int gx = x0 + xp;

    const float* wbase = g_w + (g*49)*PLANE + gy*WP + gx;

    float acc[8] = {};

    #pragma unroll 1
    for (int kh = 0; kh < 7; kh++) {
        float w7[7];
        #pragma unroll
        for (int kw = 0; kw < 7; kw++)
            w7[kw] = __ldg(wbase + (kh*7 + kw)*PLANE);

        #pragma unroll
        for (int cg = 0; cg < 2; cg++) {
            int rowbase = ((ty + kh)*2 + cg)*AGG_PCH + xp;
            #pragma unroll
            for (int kw = 0; kw < 7; kw++) {
                float4 xv = *(const float4*)&xs[(rowbase + kw)*4];
                acc[cg*4+0] += w7[kw] * xv.x;
                acc[cg*4+1] += w7[kw] * xv.y;
                acc[cg*4+2] += w7[kw] * xv.z;
                acc[cg*4+3] += w7[kw] * xv.w;
            }
        }
    }

    if (gx < 126) {
        #pragma unroll
        for (int cc = 0; cc < 8; cc++) {
            int ch = g*16 + half*8 + cc;
            dst[ch*PLANE + gy*WP + gx] = fmaxf(acc[cc], 0.f);
        }
    }
}

// ---------------------------------------------------------------------------
// conv_out v3: grid (124 rows, 2 ocg, 2 xh). block 256 = 4 colgroups x 64 oc.
// 1 oc x 16 px per thread, 64-col tile.
// ---------------------------------------------------------------------------
#define CO_XS (16*3*68)         // 3264 floats
#define CO_WS (64*16*12)        // 12288 floats
#define CO_SMEM ((CO_XS + CO_WS) * 4)

__global__ __launch_bounds__(256) void k_conv_out(const float* __restrict__ src,
    const float* __restrict__ wt, const float* __restrict__ bias,
    float* __restrict__ out)
{
    extern __shared__ float sm[];
    float* xs  = sm;            // [16][3][68]
    float* wsh = sm + CO_XS;    // [64][16][12]
    int y   = blockIdx.x;       // output row 0..123
    int ocg = blockIdx.y;       // 0..1
    int xh  = blockIdx.z;       // 0..1
    int xb0 = xh * 64;
    int tid = threadIdx.x;
    int cg = tid & 3, ol = tid >> 2;      // cg 0..3, ol 0..63
    float acc[16] = {};

    for (int icc = 0; icc < 4; icc++) {
        __syncthreads();
        for (int idx = tid; idx < CO_XS; idx += 256) {
            int ic = idx / 204; int rem = idx - ic*204;
            int r = rem / 68;   int col = rem - r*68;
            int gcol = xb0 + col;
            float v = 0.f;
            if (gcol < 126) v = src[(icc*16 + ic)*PLANE + (y + r)*WP + gcol];
            xs[idx] = v;
        }
        for (int idx = tid; idx < CO_WS; idx += 256) {
            int o = idx / 192; int rem = idx - o*192;
            int ic = rem / 12; int k = rem - ic*12;
            wsh[idx] = (k < 9) ? wt[(ocg*64 + o)*576 + (icc*16 + ic)*9 + k] : 0.f;
        }
        __syncthreads();

        #pragma unroll 2
        for (int ic = 0; ic < 16; ic++) {
            float w9[9];
            {
                const float* wb = &wsh[(ol*16 + ic)*12];
                float4 w0 = *(const float4*)wb;
                float4 w1 = *(const float4*)(wb + 4);
                w9[0]=w0.x; w9[1]=w0.y; w9[2]=w0.z; w9[3]=w0.w;
                w9[4]=w1.x; w9[5]=w1.y; w9[6]=w1.z; w9[7]=w1.w;
                w9[8]=wb[8];
            }
            #pragma unroll
            for (int kh = 0; kh < 3; kh++) {
                float xr[18];
                const float* xbp = &xs[(ic*3 + kh)*68 + cg*16];
                float4 a0 = *(const float4*)(xbp);
                float4 a1 = *(const float4*)(xbp + 4);
                float4 a2 = *(const float4*)(xbp + 8);
                float4 a3 = *(const float4*)(xbp + 12);
                float2 a4 = *(const float2*)(xbp + 16);
                xr[0]=a0.x; xr[1]=a0.y; xr[2]=a0.z; xr[3]=a0.w;
                xr[4]=a1.x; xr[5]=a1.y; xr[6]=a1.z; xr[7]=a1.w;
                xr[8]=a2.x; xr[9]=a2.y; xr[10]=a2.z; xr[11]=a2.w;
                xr[12]=a3.x; xr[13]=a3.y; xr[14]=a3.z; xr[15]=a3.w;
                xr[16]=a4.x; xr[17]=a4.y;
                #pragma unroll
                for (int kw = 0; kw < 3; kw++) {
                    float w = w9[kh*3 + kw];
                    #pragma unroll
                    for (int p = 0; p < 16; p++)
                        acc[p] += w * xr[p + kw];
                }
            }
        }
    }

    int oc = ocg*64 + ol;
    float bv = bias[oc];
    int xbase = xb0 + cg * 16;
    float* o = &out[(oc*124 + y)*124 + xbase];
    #pragma unroll
    for (int p = 0; p < 16; p++)
        if (xbase + p < 124) o[p] = acc[p] + bv;
}

// ---------------------------------------------------------------------------
extern "C" void kernel_launch(void* const* d_in, const int* in_sizes, int n_in,
                              void* d_out, int out_size)
{
    const float* input = (const float*)d_in[0];
    const float* ciw   = (const float*)d_in[1];
    const float* cib   = (const float*)d_in[2];
    const float* wr    = (const float*)d_in[3];
    const float* brr   = (const float*)d_in[4];
    const float* gmm   = (const float*)d_in[5];
    const float* bet   = (const float*)d_in[6];
    const float* mu    = (const float*)d_in[7];
    const float* var   = (const float*)d_in[8];
    const float* ws    = (const float*)d_in[9];
    const float* bs    = (const float*)d_in[10];
    const float* cow   = (const float*)d_in[11];
    const float* cob   = (const float*)d_in[12];

    float *px, *py;
    cudaGetSymbolAddress((void**)&px, g_x);
    cudaGetSymbolAddress((void**)&py, g_y);
    cudaFuncSetAttribute(k_conv_out, cudaFuncAttributeMaxDynamicSharedMemorySize, CO_SMEM);

    k_conv_in<<<dim3(63, 64), 256>>>(input, ciw, cib, px);

    float* cur = px;
    float* nxt = py;
    for (int l = 0; l < NLAYER; l++) {
        k_kgen<<<993, 256>>>(cur, wr + l*1024, brr + l*16, gmm + l*16, bet + l*16,
                             mu + l*16, var + l*16, ws + l*3136, bs + l*196);
        k_agg<<<dim3(4, 16, 8), 256>>>(cur, nxt);
        float* t = cur; cur = nxt; nxt = t;
    }
    k_conv_out<<<dim3(124, 2, 2), 256, CO_SMEM>>>(cur, cow, cob, (float*)d_out);
}

// round 7
// speedup vs baseline: 1.2575x; 1.2575x over previous
#include <cuda_runtime.h>

#define Hh 126
#define Ww 126
#define WP 128
#define NPIX (Hh*Ww)        // 15876
#define PLANE (Hh*WP)       // 16128
#define NLAYER 6

#define SWZ(b) ((b) ^ (((b) >> 3) & 0x70))

// ping-pong activation buffers + involution weight buffer
__device__ float g_x[64*PLANE];     // ~4.1 MB
__device__ float g_y[64*PLANE];     // ~4.1 MB
__device__ float g_w[196*PLANE];    // ~12.6 MB

// ---------------------------------------------------------------------------
// conv_in: (1,3,128,128) -> (1,64,126,126), 3x3 valid conv
// ---------------------------------------------------------------------------
__global__ __launch_bounds__(256) void k_conv_in(const float* __restrict__ in,
                                                 const float* __restrict__ wt,
                                                 const float* __restrict__ bias,
                                                 float* __restrict__ out)
{
    int t = blockIdx.x * 256 + threadIdx.x;      // over 126*128 padded plane
    int c = blockIdx.y;
    int y = t >> 7, x = t & 127;
    if (y >= Hh || x >= Ww) return;
    float acc = bias[c];
    const float* wc = wt + c * 27;
    #pragma unroll
    for (int i = 0; i < 3; i++)
        #pragma unroll
        for (int r = 0; r < 3; r++)
            #pragma unroll
            for (int s = 0; s < 3; s++)
                acc += wc[(i*3+r)*3+s] * in[(i*128 + (y+r))*128 + (x+s)];
    out[c*PLANE + y*WP + x] = acc;
}

// ---------------------------------------------------------------------------
// kgen v5: 256 threads / 16 pixels, 16 threads per pixel.
// NO weight staging: weights read via __ldg (warp-uniform, L1-resident).
// Only x (1024 floats) goes through smem.
// ---------------------------------------------------------------------------
__global__ __launch_bounds__(256) void k_kgen(const float* __restrict__ src,
    const float* __restrict__ wr, const float* __restrict__ br,
    const float* __restrict__ gmm, const float* __restrict__ bet,
    const float* __restrict__ mu, const float* __restrict__ var,
    const float* __restrict__ ws, const float* __restrict__ bs)
{
    __shared__ alignas(16) float xs2[16*68];     // [p][ic] pad 68
    __shared__ alignas(16) float ts[16*20];      // [p][c] pad 20

    int tid = threadIdx.x;
    int pix0 = blockIdx.x * 16;
    int p = tid & 15;
    int c = tid >> 4;

    for (int i = tid; i < 1024; i += 256) {
        int ic = i >> 4, pp = i & 15;
        int px2 = pix0 + pp;
        float v = 0.f;
        if (px2 < NPIX) {
            int y2 = px2 / 126;
            v = src[ic*PLANE + y2*WP + (px2 - y2*126)];
        }
        xs2[pp*68 + ic] = v;
    }
    __syncthreads();

    // Phase A: t(p, c) — reduce weights read directly (row c is native layout)
    {
        float a = 0.f;
        const float4* wv4 = (const float4*)(wr + c*64);
        #pragma unroll
        for (int i4 = 0; i4 < 16; i4++) {
            float4 xv = *(const float4*)&xs2[p*68 + i4*4];
            float4 wv = __ldg(&wv4[i4]);
            a += xv.x*wv.x + xv.y*wv.y + xv.z*wv.z + xv.w*wv.w;
        }
        float s = __ldg(&gmm[c]) * rsqrtf(__ldg(&var[c]) + 1e-5f);
        float h = (__ldg(&br[c]) - __ldg(&mu[c])) * s + __ldg(&bet[c]);
        ts[p*20 + c] = fmaxf(a * s + h, 0.f);
    }
    __syncthreads();

    // Phase B: j = c, c+16, ... — span weights read directly ([j][c] native)
    float t[16];
    #pragma unroll
    for (int k = 0; k < 4; k++) {
        float4 v = *(const float4*)&ts[p*20 + k*4];
        t[k*4] = v.x; t[k*4+1] = v.y; t[k*4+2] = v.z; t[k*4+3] = v.w;
    }
    int pix = pix0 + p;
    bool valid = pix < NPIX;
    int addr = 0;
    if (valid) { int yy = pix / 126; addr = yy*WP + (pix - yy*126); }

    #pragma unroll 1
    for (int j = c; j < 196; j += 16) {
        const float4* wv4 = (const float4*)(ws + j*16);
        float4 w0 = __ldg(&wv4[0]), w1 = __ldg(&wv4[1]);
        float4 w2 = __ldg(&wv4[2]), w3 = __ldg(&wv4[3]);
        float acc = __ldg(&bs[j]);
        acc += w0.x*t[0]  + w0.y*t[1]  + w0.z*t[2]  + w0.w*t[3];
        acc += w1.x*t[4]  + w1.y*t[5]  + w1.z*t[6]  + w1.w*t[7];
        acc += w2.x*t[8]  + w2.y*t[9]  + w2.z*t[10] + w2.w*t[11];
        acc += w3.x*t[12] + w3.y*t[13] + w3.z*t[14] + w3.w*t[15];
        if (valid) g_w[j*PLANE + addr] = acc;
    }
}

// ---------------------------------------------------------------------------
// agg (round-4 version): 256 threads, 32x16 tile, 8 ch/block,
// 2 px x 8 ch per thread. grid (4, 8, 8).
// ---------------------------------------------------------------------------
#define AGG_ROWS 22
#define AGG_PCH  40
#define AGG_CHUNKS (AGG_ROWS*2*AGG_PCH)

__global__ __launch_bounds__(256) void k_agg(const float* __restrict__ src,
                                             float* __restrict__ dst)
{
    __shared__ alignas(16) float xs[AGG_CHUNKS*4];

    int g    = blockIdx.z >> 1;
    int half = blockIdx.z & 1;
    int x0 = blockIdx.x * 32, y0 = blockIdx.y * 16;
    int tid = threadIdx.x;

    for (int i = tid; i < 8*22*38; i += 256) {
        int c = i / 836; int rem = i - c*836;
        int r = rem / 38; int pp = rem - r*38;
        int gy = y0 + r - 3, gx = x0 + pp - 3;
        float v = 0.f;
        if ((unsigned)gy < 126u && (unsigned)gx < 126u)
            v = src[(g*16 + half*8 + c)*PLANE + gy*WP + gx];
        int chunk = (r*2 + (c >> 2))*AGG_PCH + pp;
        int byte = chunk * 16;
        *(float*)((char*)xs + SWZ(byte) + (c & 3)*4) = v;
    }
    __syncthreads();

    int ty = tid >> 4;            // 0..15
    int xp = (tid & 15) * 2;      // 0,2,...,30
    int gy = y0 + ty;
    if (gy >= 126) return;
    int gx0 = x0 + xp;

    const float* wbase = g_w + (g*49)*PLANE + gy*WP + gx0;

    float acc[8][2];
    #pragma unroll
    for (int cc = 0; cc < 8; cc++) { acc[cc][0] = 0.f; acc[cc][1] = 0.f; }

    #pragma unroll 1
    for (int kh = 0; kh < 7; kh++) {
        float2 wv[7];
        #pragma unroll
        for (int kw = 0; kw < 7; kw++)
            wv[kw] = *(const float2*)(wbase + (kh*7 + kw)*PLANE);

        #pragma unroll
        for (int cg = 0; cg < 2; cg++) {
            int rowbase = ((ty + kh)*2 + cg)*AGG_PCH;
            float4 xq[8];
            #pragma unroll
            for (int j = 0; j < 8; j++) {
                int byte = (rowbase + xp + j) * 16;
                xq[j] = *(const float4*)((const char*)xs + SWZ(byte));
            }
            #pragma unroll
            for (int kw = 0; kw < 7; kw++) {
                #pragma unroll
                for (int q = 0; q < 2; q++) {
                    float w = q ? wv[kw].y : wv[kw].x;
                    float4 xv = xq[q + kw];
                    acc[cg*4+0][q] += w * xv.x;
                    acc[cg*4+1][q] += w * xv.y;
                    acc[cg*4+2][q] += w * xv.z;
                    acc[cg*4+3][q] += w * xv.w;
                }
            }
        }
    }

    #pragma unroll
    for (int cc = 0; cc < 8; cc++) {
        int ch = g*16 + half*8 + cc;
        float* o = dst + ch*PLANE + gy*WP + gx0;
        #pragma unroll
        for (int q = 0; q < 2; q++)
            if (gx0 + q < 126) o[q] = fmaxf(acc[cc][q], 0.f);
    }
}

// ---------------------------------------------------------------------------
// conv_out (round-4 v2): grid (124 rows, 2 oc-groups), block 256 =
// 8 colgroups x 32 oc-lanes, 2 oc x 16 px per thread. xs swizzled.
// ---------------------------------------------------------------------------
#define CO_XS (16*3*132)        // 6336 floats
#define CO_WS (64*16*12)        // 12288 floats
#define CO_SMEM ((CO_XS + CO_WS) * 4)

__global__ __launch_bounds__(256) void k_conv_out(const float* __restrict__ src,
    const float* __restrict__ wt, const float* __restrict__ bias,
    float* __restrict__ out)
{
    extern __shared__ float sm[];
    float* xs  = sm;            // [16][3][132] swizzled
    float* wsh = sm + CO_XS;    // [64][16][12]
    int y = blockIdx.x;         // output row 0..123
    int ocg = blockIdx.y;       // 0..1
    int tid = threadIdx.x;
    int cg = tid & 7, ol = tid >> 3;      // ol 0..31
    float accA[16] = {}, accB[16] = {};

    for (int icc = 0; icc < 4; icc++) {
        __syncthreads();
        for (int idx = tid; idx < CO_XS; idx += 256) {
            int ic = idx / 396; int rem = idx - ic*396;
            int r = rem / 132;  int col = rem - r*132;
            float v = 0.f;
            if (col < 126) v = src[(icc*16 + ic)*PLANE + (y + r)*WP + col];
            *(float*)((char*)xs + SWZ(idx*4)) = v;
        }
        for (int idx = tid; idx < CO_WS; idx += 256) {
            int o = idx / 192; int rem = idx - o*192;
            int ic = rem / 12; int k = rem - ic*12;
            wsh[idx] = (k < 9) ? wt[(ocg*64 + o)*576 + (icc*16 + ic)*9 + k] : 0.f;
        }
        __syncthreads();

        #pragma unroll 1
        for (int ic = 0; ic < 16; ic++) {
            float wA[9], wB[9];
            {
                const float* wb = &wsh[(ol*16 + ic)*12];
                float4 w0 = *(const float4*)wb;
                float4 w1 = *(const float4*)(wb + 4);
                wA[0]=w0.x; wA[1]=w0.y; wA[2]=w0.z; wA[3]=w0.w;
                wA[4]=w1.x; wA[5]=w1.y; wA[6]=w1.z; wA[7]=w1.w;
                wA[8]=wb[8];
                const float* wc = &wsh[((ol+32)*16 + ic)*12];
                float4 v0 = *(const float4*)wc;
                float4 v1 = *(const float4*)(wc + 4);
                wB[0]=v0.x; wB[1]=v0.y; wB[2]=v0.z; wB[3]=v0.w;
                wB[4]=v1.x; wB[5]=v1.y; wB[6]=v1.z; wB[7]=v1.w;
                wB[8]=wc[8];
            }
            #pragma unroll
            for (int kh = 0; kh < 3; kh++) {
                float xr[18];
                int base = ((ic*3 + kh)*132 + cg*16) * 4;   // byte offset
                float4 a0 = *(const float4*)((const char*)xs + SWZ(base));
                float4 a1 = *(const float4*)((const char*)xs + SWZ(base + 16));
                float4 a2 = *(const float4*)((const char*)xs + SWZ(base + 32));
                float4 a3 = *(const float4*)((const char*)xs + SWZ(base + 48));
                float2 a4 = *(const float2*)((const char*)xs + SWZ(base + 64));
                xr[0]=a0.x; xr[1]=a0.y; xr[2]=a0.z; xr[3]=a0.w;
                xr[4]=a1.x; xr[5]=a1.y; xr[6]=a1.z; xr[7]=a1.w;
                xr[8]=a2.x; xr[9]=a2.y; xr[10]=a2.z; xr[11]=a2.w;
                xr[12]=a3.x; xr[13]=a3.y; xr[14]=a3.z; xr[15]=a3.w;
                xr[16]=a4.x; xr[17]=a4.y;
                #pragma unroll
                for (int kw = 0; kw < 3; kw++) {
                    float fa = wA[kh*3 + kw];
                    float fb = wB[kh*3 + kw];
                    #pragma unroll
                    for (int p = 0; p < 16; p++) {
                        accA[p] += fa * xr[p + kw];
                        accB[p] += fb * xr[p + kw];
                    }
                }
            }
        }
    }

    int ocA = ocg*64 + ol, ocB = ocA + 32;
    float bA = bias[ocA], bB = bias[ocB];
    int xbase = cg * 16;
    float* oA = &out[(ocA*124 + y)*124 + xbase];
    float* oB = &out[(ocB*124 + y)*124 + xbase];
    #pragma unroll
    for (int p = 0; p < 16; p++)
        if (xbase + p < 124) { oA[p] = accA[p] + bA; oB[p] = accB[p] + bB; }
}

// ---------------------------------------------------------------------------
extern "C" void kernel_launch(void* const* d_in, const int* in_sizes, int n_in,
                              void* d_out, int out_size)
{
    const float* input = (const float*)d_in[0];
    const float* ciw   = (const float*)d_in[1];
    const float* cib   = (const float*)d_in[2];
    const float* wr    = (const float*)d_in[3];
    const float* brr   = (const float*)d_in[4];
    const float* gmm   = (const float*)d_in[5];
    const float* bet   = (const float*)d_in[6];
    const float* mu    = (const float*)d_in[7];
    const float* var   = (const float*)d_in[8];
    const float* ws    = (const float*)d_in[9];
    const float* bs    = (const float*)d_in[10];
    const float* cow   = (const float*)d_in[11];
    const float* cob   = (const float*)d_in[12];

    float *px, *py;
    cudaGetSymbolAddress((void**)&px, g_x);
    cudaGetSymbolAddress((void**)&py, g_y);
    cudaFuncSetAttribute(k_conv_out, cudaFuncAttributeMaxDynamicSharedMemorySize, CO_SMEM);

    k_conv_in<<<dim3(63, 64), 256>>>(input, ciw, cib, px);

    float* cur = px;
    float* nxt = py;
    for (int l = 0; l < NLAYER; l++) {
        k_kgen<<<993, 256>>>(cur, wr + l*1024, brr + l*16, gmm + l*16, bet + l*16,
                             mu + l*16, var + l*16, ws + l*3136, bs + l*196);
        k_agg<<<dim3(4, 8, 8), 256>>>(cur, nxt);
        float* t = cur; cur = nxt; nxt = t;
    }
    k_conv_out<<<dim3(124, 2), 256, CO_SMEM>>>(cur, cow, cob, (float*)d_out);
}

// round 8
// speedup vs baseline: 1.4433x; 1.1477x over previous
#include <cuda_runtime.h>

#define Hh 126
#define Ww 126
#define WP 128
#define NPIX (Hh*Ww)        // 15876
#define PLANE (Hh*WP)       // 16128
#define NLAYER 6

#define SWZ(b) ((b) ^ (((b) >> 3) & 0x70))

// ping-pong activation buffers + involution weight buffer
__device__ float g_x[64*PLANE];     // ~4.1 MB
__device__ float g_y[64*PLANE];     // ~4.1 MB
__device__ float g_w[196*PLANE];    // ~12.6 MB

// ---------------------------------------------------------------------------
// conv_in: (1,3,128,128) -> (1,64,126,126), 3x3 valid conv
// ---------------------------------------------------------------------------
__global__ __launch_bounds__(256) void k_conv_in(const float* __restrict__ in,
                                                 const float* __restrict__ wt,
                                                 const float* __restrict__ bias,
                                                 float* __restrict__ out)
{
    int t = blockIdx.x * 256 + threadIdx.x;      // over 126*128 padded plane
    int c = blockIdx.y;
    int y = t >> 7, x = t & 127;
    if (y >= Hh || x >= Ww) return;
    float acc = bias[c];
    const float* wc = wt + c * 27;
    #pragma unroll
    for (int i = 0; i < 3; i++)
        #pragma unroll
        for (int r = 0; r < 3; r++)
            #pragma unroll
            for (int s = 0; s < 3; s++)
                acc += wc[(i*3+r)*3+s] * in[(i*128 + (y+r))*128 + (x+s)];
    out[c*PLANE + y*WP + x] = acc;
}

// ---------------------------------------------------------------------------
// kgen v6: 256 threads / 32 pixels, 2 pixels per thread.
// Weights via __ldg (warp-uniform broadcast, L1-resident); each weight
// fetch now serves 2x the FMA of v5.
// ---------------------------------------------------------------------------
__global__ __launch_bounds__(256) void k_kgen(const float* __restrict__ src,
    const float* __restrict__ wr, const float* __restrict__ br,
    const float* __restrict__ gmm, const float* __restrict__ bet,
    const float* __restrict__ mu, const float* __restrict__ var,
    const float* __restrict__ ws, const float* __restrict__ bs)
{
    __shared__ alignas(16) float xs2[32*68];     // [p][ic] pad 68
    __shared__ alignas(16) float ts[32*20];      // [p][c] pad 20

    int tid = threadIdx.x;
    int pix0 = blockIdx.x * 32;
    int p = tid & 15;       // pixel slot (handles p and p+16)
    int c = tid >> 4;       // channel 0..15

    for (int i = tid; i < 2048; i += 256) {
        int ic = i >> 5, pp = i & 31;
        int px2 = pix0 + pp;
        float v = 0.f;
        if (px2 < NPIX) {
            int y2 = px2 / 126;
            v = src[ic*PLANE + y2*WP + (px2 - y2*126)];
        }
        xs2[pp*68 + ic] = v;
    }
    __syncthreads();

    // Phase A: t(c, pA) and t(c, pB)
    {
        float a0 = 0.f, a1 = 0.f;
        const float4* wv4 = (const float4*)(wr + c*64);
        #pragma unroll
        for (int i4 = 0; i4 < 16; i4++) {
            float4 wv = __ldg(&wv4[i4]);
            float4 xa = *(const float4*)&xs2[p*68 + i4*4];
            float4 xb = *(const float4*)&xs2[(p+16)*68 + i4*4];
            a0 += xa.x*wv.x + xa.y*wv.y + xa.z*wv.z + xa.w*wv.w;
            a1 += xb.x*wv.x + xb.y*wv.y + xb.z*wv.z + xb.w*wv.w;
        }
        float s = __ldg(&gmm[c]) * rsqrtf(__ldg(&var[c]) + 1e-5f);
        float h = (__ldg(&br[c]) - __ldg(&mu[c])) * s + __ldg(&bet[c]);
        ts[p*20 + c]      = fmaxf(a0 * s + h, 0.f);
        ts[(p+16)*20 + c] = fmaxf(a1 * s + h, 0.f);
    }
    __syncthreads();

    // Phase B: j = c, c+16, ... ; 2 pixels per thread
    float tA[16], tB[16];
    #pragma unroll
    for (int k = 0; k < 4; k++) {
        float4 va = *(const float4*)&ts[p*20 + k*4];
        tA[k*4] = va.x; tA[k*4+1] = va.y; tA[k*4+2] = va.z; tA[k*4+3] = va.w;
        float4 vb = *(const float4*)&ts[(p+16)*20 + k*4];
        tB[k*4] = vb.x; tB[k*4+1] = vb.y; tB[k*4+2] = vb.z; tB[k*4+3] = vb.w;
    }
    int pixA = pix0 + p, pixB = pix0 + p + 16;
    bool vA = pixA < NPIX, vB = pixB < NPIX;
    int addrA = 0, addrB = 0;
    if (vA) { int yy = pixA / 126; addrA = yy*WP + (pixA - yy*126); }
    if (vB) { int yy = pixB / 126; addrB = yy*WP + (pixB - yy*126); }

    #pragma unroll 1
    for (int j = c; j < 196; j += 16) {
        const float4* wv4 = (const float4*)(ws + j*16);
        float4 w0 = __ldg(&wv4[0]), w1 = __ldg(&wv4[1]);
        float4 w2 = __ldg(&wv4[2]), w3 = __ldg(&wv4[3]);
        float bj = __ldg(&bs[j]);
        float aA = bj, aB = bj;
        aA += w0.x*tA[0]  + w0.y*tA[1]  + w0.z*tA[2]  + w0.w*tA[3];
        aB += w0.x*tB[0]  + w0.y*tB[1]  + w0.z*tB[2]  + w0.w*tB[3];
        aA += w1.x*tA[4]  + w1.y*tA[5]  + w1.z*tA[6]  + w1.w*tA[7];
        aB += w1.x*tB[4]  + w1.y*tB[5]  + w1.z*tB[6]  + w1.w*tB[7];
        aA += w2.x*tA[8]  + w2.y*tA[9]  + w2.z*tA[10] + w2.w*tA[11];
        aB += w2.x*tB[8]  + w2.y*tB[9]  + w2.z*tB[10] + w2.w*tB[11];
        aA += w3.x*tA[12] + w3.y*tA[13] + w3.z*tA[14] + w3.w*tA[15];
        aB += w3.x*tB[12] + w3.y*tB[13] + w3.z*tB[14] + w3.w*tB[15];
        if (vA) g_w[j*PLANE + addrA] = aA;
        if (vB) g_w[j*PLANE + addrB] = aB;
    }
}

// ---------------------------------------------------------------------------
// agg (round-4 version): 256 threads, 32x16 tile, 8 ch/block,
// 2 px x 8 ch per thread. grid (4, 8, 8).
// ---------------------------------------------------------------------------
#define AGG_ROWS 22
#define AGG_PCH  40
#define AGG_CHUNKS (AGG_ROWS*2*AGG_PCH)

__global__ __launch_bounds__(256) void k_agg(const float* __restrict__ src,
                                             float* __restrict__ dst)
{
    __shared__ alignas(16) float xs[AGG_CHUNKS*4];

    int g    = blockIdx.z >> 1;
    int half = blockIdx.z & 1;
    int x0 = blockIdx.x * 32, y0 = blockIdx.y * 16;
    int tid = threadIdx.x;

    for (int i = tid; i < 8*22*38; i += 256) {
        int c = i / 836; int rem = i - c*836;
        int r = rem / 38; int pp = rem - r*38;
        int gy = y0 + r - 3, gx = x0 + pp - 3;
        float v = 0.f;
        if ((unsigned)gy < 126u && (unsigned)gx < 126u)
            v = src[(g*16 + half*8 + c)*PLANE + gy*WP + gx];
        int chunk = (r*2 + (c >> 2))*AGG_PCH + pp;
        int byte = chunk * 16;
        *(float*)((char*)xs + SWZ(byte) + (c & 3)*4) = v;
    }
    __syncthreads();

    int ty = tid >> 4;            // 0..15
    int xp = (tid & 15) * 2;      // 0,2,...,30
    int gy = y0 + ty;
    if (gy >= 126) return;
    int gx0 = x0 + xp;

    const float* wbase = g_w + (g*49)*PLANE + gy*WP + gx0;

    float acc[8][2];
    #pragma unroll
    for (int cc = 0; cc < 8; cc++) { acc[cc][0] = 0.f; acc[cc][1] = 0.f; }

    #pragma unroll 1
    for (int kh = 0; kh < 7; kh++) {
        float2 wv[7];
        #pragma unroll
        for (int kw = 0; kw < 7; kw++)
            wv[kw] = *(const float2*)(wbase + (kh*7 + kw)*PLANE);

        #pragma unroll
        for (int cg = 0; cg < 2; cg++) {
            int rowbase = ((ty + kh)*2 + cg)*AGG_PCH;
            float4 xq[8];
            #pragma unroll
            for (int j = 0; j < 8; j++) {
                int byte = (rowbase + xp + j) * 16;
                xq[j] = *(const float4*)((const char*)xs + SWZ(byte));
            }
            #pragma unroll
            for (int kw = 0; kw < 7; kw++) {
                #pragma unroll
                for (int q = 0; q < 2; q++) {
                    float w = q ? wv[kw].y : wv[kw].x;
                    float4 xv = xq[q + kw];
                    acc[cg*4+0][q] += w * xv.x;
                    acc[cg*4+1][q] += w * xv.y;
                    acc[cg*4+2][q] += w * xv.z;
                    acc[cg*4+3][q] += w * xv.w;
                }
            }
        }
    }

    #pragma unroll
    for (int cc = 0; cc < 8; cc++) {
        int ch = g*16 + half*8 + cc;
        float* o = dst + ch*PLANE + gy*WP + gx0;
        #pragma unroll
        for (int q = 0; q < 2; q++)
            if (gx0 + q < 126) o[q] = fmaxf(acc[cc][q], 0.f);
    }
}

// ---------------------------------------------------------------------------
// conv_out (round-4 v2): grid (124 rows, 2 oc-groups), block 256 =
// 8 colgroups x 32 oc-lanes, 2 oc x 16 px per thread. xs swizzled.
// ---------------------------------------------------------------------------
#define CO_XS (16*3*132)        // 6336 floats
#define CO_WS (64*16*12)        // 12288 floats
#define CO_SMEM ((CO_XS + CO_WS) * 4)

__global__ __launch_bounds__(256) void k_conv_out(const float* __restrict__ src,
    const float* __restrict__ wt, const float* __restrict__ bias,
    float* __restrict__ out)
{
    extern __shared__ float sm[];
    float* xs  = sm;            // [16][3][132] swizzled
    float* wsh = sm + CO_XS;    // [64][16][12]
    int y = blockIdx.x;         // output row 0..123
    int ocg = blockIdx.y;       // 0..1
    int tid = threadIdx.x;
    int cg = tid & 7, ol = tid >> 3;      // ol 0..31
    float accA[16] = {}, accB[16] = {};

    for (int icc = 0; icc < 4; icc++) {
        __syncthreads();
        for (int idx = tid; idx < CO_XS; idx += 256) {
            int ic = idx / 396; int rem = idx - ic*396;
            int r = rem / 132;  int col = rem - r*132;
            float v = 0.f;
            if (col < 126) v = src[(icc*16 + ic)*PLANE + (y + r)*WP + col];
            *(float*)((char*)xs + SWZ(idx*4)) = v;
        }
        for (int idx = tid; idx < CO_WS; idx += 256) {
            int o = idx / 192; int rem = idx - o*192;
            int ic = rem / 12; int k = rem - ic*12;
            wsh[idx] = (k < 9) ? wt[(ocg*64 + o)*576 + (icc*16 + ic)*9 + k] : 0.f;
        }
        __syncthreads();

        #pragma unroll 1
        for (int ic = 0; ic < 16; ic++) {
            float wA[9], wB[9];
            {
                const float* wb = &wsh[(ol*16 + ic)*12];
                float4 w0 = *(const float4*)wb;
                float4 w1 = *(const float4*)(wb + 4);
                wA[0]=w0.x; wA[1]=w0.y; wA[2]=w0.z; wA[3]=w0.w;
                wA[4]=w1.x; wA[5]=w1.y; wA[6]=w1.z; wA[7]=w1.w;
                wA[8]=wb[8];
                const float* wc = &wsh[((ol+32)*16 + ic)*12];
                float4 v0 = *(const float4*)wc;
                float4 v1 = *(const float4*)(wc + 4);
                wB[0]=v0.x; wB[1]=v0.y; wB[2]=v0.z; wB[3]=v0.w;
                wB[4]=v1.x; wB[5]=v1.y; wB[6]=v1.z; wB[7]=v1.w;
                wB[8]=wc[8];
            }
            #pragma unroll
            for (int kh = 0; kh < 3; kh++) {
                float xr[18];
                int base = ((ic*3 + kh)*132 + cg*16) * 4;   // byte offset
                float4 a0 = *(const float4*)((const char*)xs + SWZ(base));
                float4 a1 = *(const float4*)((const char*)xs + SWZ(base + 16));
                float4 a2 = *(const float4*)((const char*)xs + SWZ(base + 32));
                float4 a3 = *(const float4*)((const char*)xs + SWZ(base + 48));
                float2 a4 = *(const float2*)((const char*)xs + SWZ(base + 64));
                xr[0]=a0.x; xr[1]=a0.y; xr[2]=a0.z; xr[3]=a0.w;
                xr[4]=a1.x; xr[5]=a1.y; xr[6]=a1.z; xr[7]=a1.w;
                xr[8]=a2.x; xr[9]=a2.y; xr[10]=a2.z; xr[11]=a2.w;
                xr[12]=a3.x; xr[13]=a3.y; xr[14]=a3.z; xr[15]=a3.w;
                xr[16]=a4.x; xr[17]=a4.y;
                #pragma unroll
                for (int kw = 0; kw < 3; kw++) {
                    float fa = wA[kh*3 + kw];
                    float fb = wB[kh*3 + kw];
                    #pragma unroll
                    for (int p = 0; p < 16; p++) {
                        accA[p] += fa * xr[p + kw];
                        accB[p] += fb * xr[p + kw];
                    }
                }
            }
        }
    }

    int ocA = ocg*64 + ol, ocB = ocA + 32;
    float bA = bias[ocA], bB = bias[ocB];
    int xbase = cg * 16;
    float* oA = &out[(ocA*124 + y)*124 + xbase];
    float* oB = &out[(ocB*124 + y)*124 + xbase];
    #pragma unroll
    for (int p = 0; p < 16; p++)
        if (xbase + p < 124) { oA[p] = accA[p] + bA; oB[p] = accB[p] + bB; }
}

// ---------------------------------------------------------------------------
extern "C" void kernel_launch(void* const* d_in, const int* in_sizes, int n_in,
                              void* d_out, int out_size)
{
    const float* input = (const float*)d_in[0];
    const float* ciw   = (const float*)d_in[1];
    const float* cib   = (const float*)d_in[2];
    const float* wr    = (const float*)d_in[3];
    const float* brr   = (const float*)d_in[4];
    const float* gmm   = (const float*)d_in[5];
    const float* bet   = (const float*)d_in[6];
    const float* mu    = (const float*)d_in[7];
    const float* var   = (const float*)d_in[8];
    const float* ws    = (const float*)d_in[9];
    const float* bs    = (const float*)d_in[10];
    const float* cow   = (const float*)d_in[11];
    const float* cob   = (const float*)d_in[12];

    float *px, *py;
    cudaGetSymbolAddress((void**)&px, g_x);
    cudaGetSymbolAddress((void**)&py, g_y);
    cudaFuncSetAttribute(k_conv_out, cudaFuncAttributeMaxDynamicSharedMemorySize, CO_SMEM);

    k_conv_in<<<dim3(63, 64), 256>>>(input, ciw, cib, px);

    float* cur = px;
    float* nxt = py;
    for (int l = 0; l < NLAYER; l++) {
        k_kgen<<<497, 256>>>(cur, wr + l*1024, brr + l*16, gmm + l*16, bet + l*16,
                             mu + l*16, var + l*16, ws + l*3136, bs + l*196);
        k_agg<<<dim3(4, 8, 8), 256>>>(cur, nxt);
        float* t = cur; cur = nxt; nxt = t;
    }
    k_conv_out<<<dim3(124, 2), 256, CO_SMEM>>>(cur, cow, cob, (float*)d_out);
}